// round 14
// baseline (speedup 1.0000x reference)
#include <cuda_runtime.h>
#include <cuda_bf16.h>
#include <math.h>
#include <stdint.h>

#define NN 8192
#define DD 128
#define FLTMAX 3.402823466e38f
#define STRIDE 136   // padded bf16 row stride (272B): conflict-free LDSM rows
#define NW 256       // bitmask words per row (8192/32)

// ---------------- device-global scratch (no runtime allocation) -------------
__device__ float          g_centers[(size_t)NN * DD];
__device__ __nv_bfloat16  g_centersB[(size_t)NN * DD];
__device__ __nv_bfloat16  g_Xb [(size_t)NN * DD];   // X bf16 row-major [j][d]
__device__ __nv_bfloat16  g_XbT[(size_t)DD * NN];   // X^T bf16 [d][j]
__device__ uint32_t       g_maskBits[(size_t)NN * NW]; // packed mask bits
__device__ float          g_cntF[NN];
__device__ float          g_x2[NN];
__device__ float          g_c2[NN];
__device__ float          g_part[(size_t)4 * NN * DD];
__device__ float          g_blockBest[(size_t)4 * NN];
__device__ int            g_blockIdx [(size_t)4 * NN];

// ---------------- MMA / LDSM / cp.async helpers ------------------------------
__device__ __forceinline__ void mma16816(float c[4],
                                         uint32_t a0, uint32_t a1, uint32_t a2, uint32_t a3,
                                         uint32_t b0, uint32_t b1) {
    asm volatile(
        "mma.sync.aligned.m16n8k16.row.col.f32.bf16.bf16.f32 "
        "{%0,%1,%2,%3}, {%4,%5,%6,%7}, {%8,%9}, {%0,%1,%2,%3};"
        : "+f"(c[0]), "+f"(c[1]), "+f"(c[2]), "+f"(c[3])
        : "r"(a0), "r"(a1), "r"(a2), "r"(a3), "r"(b0), "r"(b1));
}

__device__ __forceinline__ void ldsm4(uint32_t r[4], uint32_t addr) {
    asm volatile("ldmatrix.sync.aligned.m8n8.x4.shared.b16 {%0,%1,%2,%3}, [%4];"
        : "=r"(r[0]), "=r"(r[1]), "=r"(r[2]), "=r"(r[3]) : "r"(addr));
}

__device__ __forceinline__ uint32_t smem_u32(const void* p) {
    uint32_t a;
    asm("{ .reg .u64 t; cvta.to.shared.u64 t, %1; cvt.u32.u64 %0, t; }" : "=r"(a) : "l"(p));
    return a;
}

#define CP_ASYNC16(dst, src) \
    asm volatile("cp.async.cg.shared.global [%0], [%1], 16;" :: "r"(dst), "l"(src))
#define CP_COMMIT() asm volatile("cp.async.commit_group;" ::: "memory")
#define CP_WAIT0()  asm volatile("cp.async.wait_group 0;" ::: "memory")

// two mask bits (i, i+1) -> packed bf16x2 {0|1, 0|1}
__device__ __forceinline__ uint32_t pack2(uint32_t m, int i) {
    return ((m >> i) & 1u) * 0x3F80u + ((m >> (i + 1)) & 1u) * 0x3F800000u;
}

// ---------------------------------------------------------------------------
// pack: similarity int32 -> bitmask + per-row count. warp per row.
// ---------------------------------------------------------------------------
__global__ __launch_bounds__(256) void pack_kernel(const int* __restrict__ S) {
    int row = blockIdx.x * 8 + (threadIdx.x >> 5);
    int lane = threadIdx.x & 31;
    const int* src = S + (size_t)row * NN;
    uint32_t* dst = g_maskBits + (size_t)row * NW;
    int cnt = 0;
#pragma unroll 4
    for (int it = 0; it < 64; it++) {
        int base = it * 128;
        uint32_t b0 = __ballot_sync(0xffffffffu, src[base + lane] != 0);
        uint32_t b1 = __ballot_sync(0xffffffffu, src[base + 32 + lane] != 0);
        uint32_t b2 = __ballot_sync(0xffffffffu, src[base + 64 + lane] != 0);
        uint32_t b3 = __ballot_sync(0xffffffffu, src[base + 96 + lane] != 0);
        if (lane == 0) {
            *reinterpret_cast<uint4*>(dst + it * 4) = make_uint4(b0, b1, b2, b3);
            cnt += __popc(b0) + __popc(b1) + __popc(b2) + __popc(b3);
        }
    }
    if (lane == 0) g_cntF[row] = (float)cnt;
}

// ---------------------------------------------------------------------------
// prep: Xb (bf16), XbT (bf16 transposed) via smem tile transpose
// ---------------------------------------------------------------------------
__global__ __launch_bounds__(256) void prep_kernel(const float* __restrict__ X) {
    __shared__ float tile[32][33];
    int tx = threadIdx.x & 31, ty = threadIdx.x >> 5;
    int j0 = blockIdx.x * 32, d0 = blockIdx.y * 32;
#pragma unroll
    for (int jr = ty; jr < 32; jr += 8) {
        float v = X[(size_t)(j0 + jr) * DD + d0 + tx];
        tile[jr][tx] = v;
        g_Xb[(size_t)(j0 + jr) * DD + d0 + tx] = __float2bfloat16_rn(v);
    }
    __syncthreads();
#pragma unroll
    for (int dr = ty; dr < 32; dr += 8)
        g_XbT[(size_t)(d0 + dr) * NN + j0 + tx] = __float2bfloat16_rn(tile[tx][dr]);
}

__global__ __launch_bounds__(256) void x2_kernel(const float* __restrict__ X) {
    int warp = blockIdx.x * 8 + (threadIdx.x >> 5);
    int lane = threadIdx.x & 31;
    float4 a = reinterpret_cast<const float4*>(X + (size_t)warp * DD)[lane];
    float s = a.x * a.x + a.y * a.y + a.z * a.z + a.w * a.w;
#pragma unroll
    for (int o = 16; o; o >>= 1) s += __shfl_xor_sync(0xffffffffu, s, o);
    if (lane == 0) g_x2[warp] = s;
}

// ---------------------------------------------------------------------------
// centers HMMA: part[128 rows, 128 dims] = mask_bf16 @ XbT over K-split 2048
// grid (64 mb, 4 split) = 256 CTAs, 512 threads (16 warps 4x4), 2 CTAs/SM.
// cp.async double-buffered B + mask words; A expanded into smem per iter.
// ---------------------------------------------------------------------------
#define CEN_SM_B(buf)  (34816 + (buf) * 34816)
#define CEN_SM_M(buf)  (104448 + (buf) * 2048)
#define CEN_SM_TOTAL   108544

__global__ __launch_bounds__(512, 2) void centers_mma() {
    extern __shared__ __align__(16) char sm[];
    const uint32_t smb = smem_u32(sm);
    __nv_bfloat16* As = reinterpret_cast<__nv_bfloat16*>(sm);

    const int tid = threadIdx.x;
    const int wid = tid >> 5, lane = tid & 31;
    const int wm = wid >> 2, wn = wid & 3;          // 4 x 4 warps
    const int rowBase = blockIdx.x * 128;
    const int kBase = blockIdx.y * 2048;

    const int lr = tid >> 2;          // row 0..127
    const int q  = tid & 3;           // 32-elem quarter

    const int l7 = lane & 7, lid8 = lane >> 3;
    uint32_t aoff[2], boffRel[2];
#pragma unroll
    for (int mt = 0; mt < 2; mt++)
        aoff[mt] = smb + (uint32_t)((wm * 32 + mt * 16 + (lid8 & 1) * 8 + l7) * STRIDE * 2 + (lid8 >> 1) * 16);
#pragma unroll
    for (int np = 0; np < 2; np++)
        boffRel[np] = (uint32_t)((wn * 32 + np * 16 + (lid8 >> 1) * 8 + l7) * STRIDE * 2 + (lid8 & 1) * 16);

    float acc[2][4][4];
#pragma unroll
    for (int mt = 0; mt < 2; mt++)
#pragma unroll
        for (int nt = 0; nt < 4; nt++)
#pragma unroll
            for (int qq = 0; qq < 4; qq++) acc[mt][nt][qq] = 0.f;

    // prologue: B + M for iter 0
    {
        uint32_t bdst = smb + CEN_SM_B(0) + (uint32_t)(lr * STRIDE + q * 32) * 2;
        const __nv_bfloat16* bsrc = g_XbT + (size_t)lr * NN + kBase + q * 32;
#pragma unroll
        for (int u = 0; u < 4; u++) CP_ASYNC16(bdst + u * 16, bsrc + u * 8);
        if (tid < 128)
            CP_ASYNC16(smb + CEN_SM_M(0) + tid * 16,
                       g_maskBits + (size_t)(rowBase + tid) * NW + (kBase >> 5));
        CP_COMMIT();
    }

    for (int it = 0; it < 16; it++) {
        const int buf = it & 1;
        CP_WAIT0();
        __syncthreads();

        if (it + 1 < 16) {
            const int k0 = kBase + (it + 1) * 128;
            uint32_t bdst = smb + CEN_SM_B(buf ^ 1) + (uint32_t)(lr * STRIDE + q * 32) * 2;
            const __nv_bfloat16* bsrc = g_XbT + (size_t)lr * NN + k0 + q * 32;
#pragma unroll
            for (int u = 0; u < 4; u++) CP_ASYNC16(bdst + u * 16, bsrc + u * 8);
            if (tid < 128)
                CP_ASYNC16(smb + CEN_SM_M(buf ^ 1) + tid * 16,
                           g_maskBits + (size_t)(rowBase + tid) * NW + (k0 >> 5));
            CP_COMMIT();
        }

        // expand A tile: one 32-bit mask word per thread -> 32 bf16 into As
        {
            uint32_t mword = reinterpret_cast<const uint32_t*>(sm + CEN_SM_M(buf))[tid];
            __nv_bfloat16* arow = As + lr * STRIDE + q * 32;
#pragma unroll
            for (int u = 0; u < 4; u++)
                *reinterpret_cast<uint4*>(arow + u * 8) =
                    make_uint4(pack2(mword, u * 8), pack2(mword, u * 8 + 2),
                               pack2(mword, u * 8 + 4), pack2(mword, u * 8 + 6));
        }
        __syncthreads();

        const uint32_t bbase = smb + CEN_SM_B(buf);
#pragma unroll
        for (int ks = 0; ks < 8; ks++) {
            const uint32_t kb = ks * 32;
            uint32_t a[2][4], b[2][4];
#pragma unroll
            for (int mt = 0; mt < 2; mt++) ldsm4(a[mt], aoff[mt] + kb);
#pragma unroll
            for (int np = 0; np < 2; np++) ldsm4(b[np], bbase + boffRel[np] + kb);
#pragma unroll
            for (int mt = 0; mt < 2; mt++)
#pragma unroll
                for (int nt = 0; nt < 4; nt++)
                    mma16816(acc[mt][nt], a[mt][0], a[mt][1], a[mt][2], a[mt][3],
                             b[nt >> 1][(nt & 1) * 2], b[nt >> 1][(nt & 1) * 2 + 1]);
        }
    }

    const int g = lane >> 2, tig = lane & 3;
#pragma unroll
    for (int mt = 0; mt < 2; mt++)
#pragma unroll
        for (int h = 0; h < 2; h++) {
            int grow = rowBase + wm * 32 + mt * 16 + h * 8 + g;
#pragma unroll
            for (int nt = 0; nt < 4; nt++) {
                int col = wn * 32 + nt * 8 + tig * 2;
                float2 v = make_float2(acc[mt][nt][h * 2], acc[mt][nt][h * 2 + 1]);
                *reinterpret_cast<float2*>(g_part + ((size_t)blockIdx.y * NN + grow) * DD + col) = v;
            }
        }
}

// ---------------------------------------------------------------------------
// centers combine: sum 4 split partials, /count, write fp32 + bf16 + c2
// ---------------------------------------------------------------------------
__global__ __launch_bounds__(128) void centers_combine() {
    int row = blockIdx.x * 4 + (threadIdx.x >> 5);
    int lane = threadIdx.x & 31;
    float inv = 1.0f / g_cntF[row];
    float4 s = make_float4(0.f, 0.f, 0.f, 0.f);
#pragma unroll
    for (int sp = 0; sp < 4; sp++) {
        float4 p = reinterpret_cast<const float4*>(g_part + ((size_t)sp * NN + row) * DD)[lane];
        s.x += p.x; s.y += p.y; s.z += p.z; s.w += p.w;
    }
    s.x *= inv; s.y *= inv; s.z *= inv; s.w *= inv;
    reinterpret_cast<float4*>(g_centers + (size_t)row * DD)[lane] = s;
    __nv_bfloat162 lo = __floats2bfloat162_rn(s.x, s.y);
    __nv_bfloat162 hi = __floats2bfloat162_rn(s.z, s.w);
    uint2 packed = make_uint2(*reinterpret_cast<uint32_t*>(&lo), *reinterpret_cast<uint32_t*>(&hi));
    reinterpret_cast<uint2*>(g_centersB + (size_t)row * DD)[lane] = packed;
    float c2 = s.x * s.x + s.y * s.y + s.z * s.z + s.w * s.w;
#pragma unroll
    for (int o = 16; o; o >>= 1) c2 += __shfl_xor_sync(0xffffffffu, c2, o);
    if (lane == 0) g_c2[row] = c2;
}

// ---------------------------------------------------------------------------
// argmin HMMA: dot[128 rows, 128 j] = centersB @ Xb^T (K=128), fused argmin.
// grid (4 nb, 64 mb) = 256 CTAs (single wave at 2 CTAs/SM), 512 threads
// (16 warps 4x4); 16 j-tiles/CTA, cp.async double-buffered B+masks.
// ---------------------------------------------------------------------------
#define ARG_SM_B(buf)  (34816 + (buf) * 34816)
#define ARG_SM_M(buf)  (104448 + (buf) * 2048)
#define ARG_SM_X2      108544
#define ARG_SM_C2      116736
#define ARG_SM_RV      104448
#define ARG_SM_RI      106496
#define ARG_SM_TOTAL   117248

__global__ __launch_bounds__(512, 2) void argmin_mma() {
    extern __shared__ __align__(16) char sm[];
    const uint32_t smb = smem_u32(sm);
    float* x2s = reinterpret_cast<float*>(sm + ARG_SM_X2);   // 2048 floats
    float* c2s = reinterpret_cast<float*>(sm + ARG_SM_C2);
    float* redV = reinterpret_cast<float*>(sm + ARG_SM_RV);
    int*   redI = reinterpret_cast<int*>(sm + ARG_SM_RI);

    const int tid = threadIdx.x;
    const int wid = tid >> 5, lane = tid & 31;
    const int wm = wid >> 2, wn = wid & 3;
    const int g = lane >> 2, tig = lane & 3;
    const int mBase = blockIdx.y * 128;
    const int jBase0 = blockIdx.x * 2048;

    const int lr = tid >> 2, q = tid & 3;

    // prologue: A, B(jt0), M(jt0), x2 (2048 floats), c2 (128 floats)
    {
        uint32_t adst = smb + (uint32_t)(lr * STRIDE + q * 32) * 2;
        const __nv_bfloat16* asrc = g_centersB + (size_t)(mBase + lr) * DD + q * 32;
#pragma unroll
        for (int u = 0; u < 4; u++) CP_ASYNC16(adst + u * 16, asrc + u * 8);
        uint32_t bdst = smb + ARG_SM_B(0) + (uint32_t)(lr * STRIDE + q * 32) * 2;
        const __nv_bfloat16* bsrc = g_Xb + (size_t)(jBase0 + lr) * DD + q * 32;
#pragma unroll
        for (int u = 0; u < 4; u++) CP_ASYNC16(bdst + u * 16, bsrc + u * 8);
        if (tid < 128)
            CP_ASYNC16(smb + ARG_SM_M(0) + tid * 16,
                       g_maskBits + (size_t)(mBase + tid) * NW + (jBase0 >> 5));
        CP_ASYNC16(smb + ARG_SM_X2 + tid * 16, g_x2 + jBase0 + tid * 4);
        if (tid < 32) CP_ASYNC16(smb + ARG_SM_C2 + tid * 16, g_c2 + mBase + tid * 4);
        CP_COMMIT();
    }

    const int l7 = lane & 7, lid8 = lane >> 3;
    uint32_t aoff[2], boffRel[2];
#pragma unroll
    for (int mt = 0; mt < 2; mt++)
        aoff[mt] = smb + (uint32_t)((wm * 32 + mt * 16 + (lid8 & 1) * 8 + l7) * STRIDE * 2 + (lid8 >> 1) * 16);
#pragma unroll
    for (int np = 0; np < 2; np++)
        boffRel[np] = (uint32_t)((wn * 32 + np * 16 + (lid8 >> 1) * 8 + l7) * STRIDE * 2 + (lid8 & 1) * 16);

    float best[2][2];
    int   bidx[2][2];
#pragma unroll
    for (int mt = 0; mt < 2; mt++)
#pragma unroll
        for (int h = 0; h < 2; h++) { best[mt][h] = FLTMAX; bidx[mt][h] = 0x7FFFFFFF; }

    for (int jt = 0; jt < 16; jt++) {
        const int buf = jt & 1;
        const int jBase = jBase0 + jt * 128;
        CP_WAIT0();
        __syncthreads();

        if (jt + 1 < 16) {
            const int jn = jBase0 + (jt + 1) * 128;
            uint32_t bdst = smb + ARG_SM_B(buf ^ 1) + (uint32_t)(lr * STRIDE + q * 32) * 2;
            const __nv_bfloat16* bsrc = g_Xb + (size_t)(jn + lr) * DD + q * 32;
#pragma unroll
            for (int u = 0; u < 4; u++) CP_ASYNC16(bdst + u * 16, bsrc + u * 8);
            if (tid < 128)
                CP_ASYNC16(smb + ARG_SM_M(buf ^ 1) + tid * 16,
                           g_maskBits + (size_t)(mBase + tid) * NW + (jn >> 5));
            CP_COMMIT();
        }

        float acc[2][4][4];
#pragma unroll
        for (int mt = 0; mt < 2; mt++)
#pragma unroll
            for (int nt = 0; nt < 4; nt++)
#pragma unroll
                for (int qq = 0; qq < 4; qq++) acc[mt][nt][qq] = 0.f;

        const uint32_t bbase = smb + ARG_SM_B(buf);
#pragma unroll
        for (int ks = 0; ks < 8; ks++) {
            const uint32_t kb = ks * 32;
            uint32_t a[2][4], b[2][4];
#pragma unroll
            for (int mt = 0; mt < 2; mt++) ldsm4(a[mt], aoff[mt] + kb);
#pragma unroll
            for (int np = 0; np < 2; np++) ldsm4(b[np], bbase + boffRel[np] + kb);
#pragma unroll
            for (int mt = 0; mt < 2; mt++)
#pragma unroll
                for (int nt = 0; nt < 4; nt++)
                    mma16816(acc[mt][nt], a[mt][0], a[mt][1], a[mt][2], a[mt][3],
                             b[nt >> 1][(nt & 1) * 2], b[nt >> 1][(nt & 1) * 2 + 1]);
        }

        // fused argmin update; mask words from smem
        const uint32_t* Msm = reinterpret_cast<const uint32_t*>(sm + ARG_SM_M(buf));
#pragma unroll
        for (int mt = 0; mt < 2; mt++)
#pragma unroll
            for (int h = 0; h < 2; h++) {
                int lrow = wm * 32 + mt * 16 + h * 8 + g;
                float negc2 = -c2s[lrow];
                uint32_t mw = Msm[lrow * 4 + wn];
                float bb = best[mt][h];
                int bi = bidx[mt][h];
#pragma unroll
                for (int nt = 0; nt < 4; nt++) {
                    int bpos = nt * 8 + tig * 2;
                    int lcol = wn * 32 + bpos;
                    float v0 = fmaxf(fmaf(-2.f, acc[mt][nt][h * 2 + 0], x2s[jt * 128 + lcol + 0]), negc2);
                    float v1 = fmaxf(fmaf(-2.f, acc[mt][nt][h * 2 + 1], x2s[jt * 128 + lcol + 1]), negc2);
                    if ((mw >> bpos) & 1u) v0 = FLTMAX;
                    if ((mw >> (bpos + 1)) & 1u) v1 = FLTMAX;
                    if (v0 < bb) { bb = v0; bi = jBase + lcol; }
                    if (v1 < bb) { bb = v1; bi = jBase + lcol + 1; }
                }
                best[mt][h] = bb;
                bidx[mt][h] = bi;
            }
    }

    // barrier: mask region is about to be reused as reduction scratch
    __syncthreads();

    // final reductions
#pragma unroll
    for (int mt = 0; mt < 2; mt++)
#pragma unroll
        for (int h = 0; h < 2; h++) {
            float bb = best[mt][h];
            int bi = bidx[mt][h];
#pragma unroll
            for (int o = 1; o < 4; o <<= 1) {
                float v = __shfl_down_sync(0xffffffffu, bb, o);
                int   i = __shfl_down_sync(0xffffffffu, bi, o);
                if (v < bb || (v == bb && i < bi)) { bb = v; bi = i; }
            }
            if (tig == 0) {
                int lrow = wm * 32 + mt * 16 + h * 8 + g;
                redV[lrow * 4 + wn] = bb;
                redI[lrow * 4 + wn] = bi;
            }
        }
    __syncthreads();

    if (tid < 128) {
        float bb = redV[tid * 4];
        int bi = redI[tid * 4];
#pragma unroll
        for (int w = 1; w < 4; w++) {
            float v = redV[tid * 4 + w];
            int   i = redI[tid * 4 + w];
            if (v < bb || (v == bb && i < bi)) { bb = v; bi = i; }
        }
        g_blockBest[(size_t)blockIdx.x * NN + mBase + tid] = bb;
        g_blockIdx [(size_t)blockIdx.x * NN + mBase + tid] = bi;
    }
}

// ---------------------------------------------------------------------------
// fused combine + loss + global mean: warp per anchor; block partial sum is
// atomically added to out[0] (pre-zeroed by cudaMemsetAsync).
// ---------------------------------------------------------------------------
__global__ __launch_bounds__(128) void combine_loss_kernel(const float* __restrict__ X,
                                                           float* __restrict__ out) {
    __shared__ float warpSum[4];
    int a = blockIdx.x * 4 + (threadIdx.x >> 5);
    int lane = threadIdx.x & 31;
    float bv = FLTMAX;
    int bi = 0x7FFFFFFF;
    if (lane < 4) {
        bv = g_blockBest[(size_t)lane * NN + a];
        bi = g_blockIdx [(size_t)lane * NN + a];
    }
#pragma unroll
    for (int o = 2; o; o >>= 1) {
        float v = __shfl_down_sync(0xffffffffu, bv, o);
        int   i = __shfl_down_sync(0xffffffffu, bi, o);
        if (v < bv || (v == bv && i < bi)) { bv = v; bi = i; }
    }
    bi = __shfl_sync(0xffffffffu, bi, 0);

    float4 cv = reinterpret_cast<const float4*>(g_centers + (size_t)a * DD)[lane];
    float4 xv = reinterpret_cast<const float4*>(X + (size_t)a * DD)[lane];
    float4 nv = reinterpret_cast<const float4*>(X + (size_t)bi * DD)[lane];
    const float EPS = 1e-6f;
    float t, sap = 0.f, san = 0.f;
    t = cv.x - xv.x + EPS; sap += t * t;
    t = cv.y - xv.y + EPS; sap += t * t;
    t = cv.z - xv.z + EPS; sap += t * t;
    t = cv.w - xv.w + EPS; sap += t * t;
    t = cv.x - nv.x + EPS; san += t * t;
    t = cv.y - nv.y + EPS; san += t * t;
    t = cv.z - nv.z + EPS; san += t * t;
    t = cv.w - nv.w + EPS; san += t * t;
#pragma unroll
    for (int o = 16; o; o >>= 1) {
        sap += __shfl_xor_sync(0xffffffffu, sap, o);
        san += __shfl_xor_sync(0xffffffffu, san, o);
    }
    if (lane == 0)
        warpSum[threadIdx.x >> 5] = fmaxf(sqrtf(sap) - sqrtf(san) + 0.3f, 0.f);
    __syncthreads();
    if (threadIdx.x == 0) {
        float s = (warpSum[0] + warpSum[1]) + (warpSum[2] + warpSum[3]);
        atomicAdd(out, s * (1.0f / NN));
    }
}

// ---------------------------------------------------------------------------
extern "C" void kernel_launch(void* const* d_in, const int* in_sizes, int n_in,
                              void* d_out, int out_size) {
    const float* X;
    const int* S;
    if (in_sizes[0] == NN * DD) {
        X = (const float*)d_in[0];
        S = (const int*)d_in[1];
    } else {
        X = (const float*)d_in[1];
        S = (const int*)d_in[0];
    }

    cudaFuncSetAttribute(centers_mma, cudaFuncAttributeMaxDynamicSharedMemorySize, CEN_SM_TOTAL);
    cudaFuncSetAttribute(argmin_mma, cudaFuncAttributeMaxDynamicSharedMemorySize, ARG_SM_TOTAL);

    cudaMemsetAsync(d_out, 0, sizeof(float), 0);

    pack_kernel<<<NN / 8, 256>>>(S);
    prep_kernel<<<dim3(NN / 32, DD / 32), 256>>>(X);
    x2_kernel<<<NN / 8, 256>>>(X);
    centers_mma<<<dim3(64, 4), 512, CEN_SM_TOTAL>>>();
    centers_combine<<<NN / 4, 128>>>();
    argmin_mma<<<dim3(4, 64), 512, ARG_SM_TOTAL>>>();
    combine_loss_kernel<<<NN / 4, 128>>>(X, (float*)d_out);
}

// round 15
// speedup vs baseline: 1.0530x; 1.0530x over previous
#include <cuda_runtime.h>
#include <cuda_bf16.h>
#include <math.h>
#include <stdint.h>

#define NN 8192
#define DD 128
#define FLTMAX 3.402823466e38f
#define STRIDE 136   // padded bf16 row stride (272B): conflict-free LDSM rows
#define NW 256       // bitmask words per row (8192/32)

// ---------------- device-global scratch (no runtime allocation) -------------
__device__ float          g_centers[(size_t)NN * DD];
__device__ __nv_bfloat16  g_centersB[(size_t)NN * DD];
__device__ __nv_bfloat16  g_Xb [(size_t)NN * DD];   // X bf16 row-major [j][d]
__device__ __nv_bfloat16  g_XbT[(size_t)DD * NN];   // X^T bf16 [d][j]
__device__ uint32_t       g_maskBits[(size_t)NN * NW]; // packed mask bits
__device__ float          g_cntF[NN];
__device__ float          g_x2[NN];
__device__ float          g_c2[NN];
__device__ float          g_part[(size_t)4 * NN * DD];
__device__ float          g_blockBest[(size_t)8 * NN];
__device__ int            g_blockIdx [(size_t)8 * NN];

// ---------------- MMA / LDSM / cp.async helpers ------------------------------
__device__ __forceinline__ void mma16816(float c[4],
                                         uint32_t a0, uint32_t a1, uint32_t a2, uint32_t a3,
                                         uint32_t b0, uint32_t b1) {
    asm volatile(
        "mma.sync.aligned.m16n8k16.row.col.f32.bf16.bf16.f32 "
        "{%0,%1,%2,%3}, {%4,%5,%6,%7}, {%8,%9}, {%0,%1,%2,%3};"
        : "+f"(c[0]), "+f"(c[1]), "+f"(c[2]), "+f"(c[3])
        : "r"(a0), "r"(a1), "r"(a2), "r"(a3), "r"(b0), "r"(b1));
}

__device__ __forceinline__ void ldsm4(uint32_t r[4], uint32_t addr) {
    asm volatile("ldmatrix.sync.aligned.m8n8.x4.shared.b16 {%0,%1,%2,%3}, [%4];"
        : "=r"(r[0]), "=r"(r[1]), "=r"(r[2]), "=r"(r[3]) : "r"(addr));
}

__device__ __forceinline__ uint32_t smem_u32(const void* p) {
    uint32_t a;
    asm("{ .reg .u64 t; cvta.to.shared.u64 t, %1; cvt.u32.u64 %0, t; }" : "=r"(a) : "l"(p));
    return a;
}

#define CP_ASYNC16(dst, src) \
    asm volatile("cp.async.cg.shared.global [%0], [%1], 16;" :: "r"(dst), "l"(src))
#define CP_COMMIT() asm volatile("cp.async.commit_group;" ::: "memory")
#define CP_WAIT0()  asm volatile("cp.async.wait_group 0;" ::: "memory")

// two mask bits (i, i+1) -> packed bf16x2 {0|1, 0|1}
__device__ __forceinline__ uint32_t pack2(uint32_t m, int i) {
    return ((m >> i) & 1u) * 0x3F80u + ((m >> (i + 1)) & 1u) * 0x3F800000u;
}

// ---------------------------------------------------------------------------
// pack: similarity int32 -> bitmask + per-row count. warp per row.
// ---------------------------------------------------------------------------
__global__ __launch_bounds__(256) void pack_kernel(const int* __restrict__ S) {
    int row = blockIdx.x * 8 + (threadIdx.x >> 5);
    int lane = threadIdx.x & 31;
    const int* src = S + (size_t)row * NN;
    uint32_t* dst = g_maskBits + (size_t)row * NW;
    int cnt = 0;
#pragma unroll 4
    for (int it = 0; it < 64; it++) {
        int base = it * 128;
        uint32_t b0 = __ballot_sync(0xffffffffu, src[base + lane] != 0);
        uint32_t b1 = __ballot_sync(0xffffffffu, src[base + 32 + lane] != 0);
        uint32_t b2 = __ballot_sync(0xffffffffu, src[base + 64 + lane] != 0);
        uint32_t b3 = __ballot_sync(0xffffffffu, src[base + 96 + lane] != 0);
        if (lane == 0) {
            *reinterpret_cast<uint4*>(dst + it * 4) = make_uint4(b0, b1, b2, b3);
            cnt += __popc(b0) + __popc(b1) + __popc(b2) + __popc(b3);
        }
    }
    if (lane == 0) g_cntF[row] = (float)cnt;
}

// ---------------------------------------------------------------------------
// prep: Xb (bf16), XbT (bf16 transposed) via smem tile transpose
// ---------------------------------------------------------------------------
__global__ __launch_bounds__(256) void prep_kernel(const float* __restrict__ X) {
    __shared__ float tile[32][33];
    int tx = threadIdx.x & 31, ty = threadIdx.x >> 5;
    int j0 = blockIdx.x * 32, d0 = blockIdx.y * 32;
#pragma unroll
    for (int jr = ty; jr < 32; jr += 8) {
        float v = X[(size_t)(j0 + jr) * DD + d0 + tx];
        tile[jr][tx] = v;
        g_Xb[(size_t)(j0 + jr) * DD + d0 + tx] = __float2bfloat16_rn(v);
    }
    __syncthreads();
#pragma unroll
    for (int dr = ty; dr < 32; dr += 8)
        g_XbT[(size_t)(d0 + dr) * NN + j0 + tx] = __float2bfloat16_rn(tile[tx][dr]);
}

__global__ __launch_bounds__(256) void x2_kernel(const float* __restrict__ X) {
    int warp = blockIdx.x * 8 + (threadIdx.x >> 5);
    int lane = threadIdx.x & 31;
    float4 a = reinterpret_cast<const float4*>(X + (size_t)warp * DD)[lane];
    float s = a.x * a.x + a.y * a.y + a.z * a.z + a.w * a.w;
#pragma unroll
    for (int o = 16; o; o >>= 1) s += __shfl_xor_sync(0xffffffffu, s, o);
    if (lane == 0) g_x2[warp] = s;
}

// ---------------------------------------------------------------------------
// centers HMMA: part[128 rows, 128 dims] = mask_bf16 @ XbT over K-split 2048
// grid (64 mb, 4 split) = 256 CTAs, 512 threads (16 warps 4x4), 2 CTAs/SM.
// cp.async double-buffered B + mask words; A expanded into smem per iter.
// ---------------------------------------------------------------------------
#define CEN_SM_B(buf)  (34816 + (buf) * 34816)
#define CEN_SM_M(buf)  (104448 + (buf) * 2048)
#define CEN_SM_TOTAL   108544

__global__ __launch_bounds__(512, 2) void centers_mma() {
    extern __shared__ __align__(16) char sm[];
    const uint32_t smb = smem_u32(sm);
    __nv_bfloat16* As = reinterpret_cast<__nv_bfloat16*>(sm);

    const int tid = threadIdx.x;
    const int wid = tid >> 5, lane = tid & 31;
    const int wm = wid >> 2, wn = wid & 3;          // 4 x 4 warps
    const int rowBase = blockIdx.x * 128;
    const int kBase = blockIdx.y * 2048;

    const int lr = tid >> 2;          // row 0..127
    const int q  = tid & 3;           // 32-elem quarter

    const int l7 = lane & 7, lid8 = lane >> 3;
    uint32_t aoff[2], boffRel[2];
#pragma unroll
    for (int mt = 0; mt < 2; mt++)
        aoff[mt] = smb + (uint32_t)((wm * 32 + mt * 16 + (lid8 & 1) * 8 + l7) * STRIDE * 2 + (lid8 >> 1) * 16);
#pragma unroll
    for (int np = 0; np < 2; np++)
        boffRel[np] = (uint32_t)((wn * 32 + np * 16 + (lid8 >> 1) * 8 + l7) * STRIDE * 2 + (lid8 & 1) * 16);

    float acc[2][4][4];
#pragma unroll
    for (int mt = 0; mt < 2; mt++)
#pragma unroll
        for (int nt = 0; nt < 4; nt++)
#pragma unroll
            for (int qq = 0; qq < 4; qq++) acc[mt][nt][qq] = 0.f;

    // prologue: B + M for iter 0
    {
        uint32_t bdst = smb + CEN_SM_B(0) + (uint32_t)(lr * STRIDE + q * 32) * 2;
        const __nv_bfloat16* bsrc = g_XbT + (size_t)lr * NN + kBase + q * 32;
#pragma unroll
        for (int u = 0; u < 4; u++) CP_ASYNC16(bdst + u * 16, bsrc + u * 8);
        if (tid < 128)
            CP_ASYNC16(smb + CEN_SM_M(0) + tid * 16,
                       g_maskBits + (size_t)(rowBase + tid) * NW + (kBase >> 5));
        CP_COMMIT();
    }

    for (int it = 0; it < 16; it++) {
        const int buf = it & 1;
        CP_WAIT0();
        __syncthreads();

        if (it + 1 < 16) {
            const int k0 = kBase + (it + 1) * 128;
            uint32_t bdst = smb + CEN_SM_B(buf ^ 1) + (uint32_t)(lr * STRIDE + q * 32) * 2;
            const __nv_bfloat16* bsrc = g_XbT + (size_t)lr * NN + k0 + q * 32;
#pragma unroll
            for (int u = 0; u < 4; u++) CP_ASYNC16(bdst + u * 16, bsrc + u * 8);
            if (tid < 128)
                CP_ASYNC16(smb + CEN_SM_M(buf ^ 1) + tid * 16,
                           g_maskBits + (size_t)(rowBase + tid) * NW + (k0 >> 5));
            CP_COMMIT();
        }

        // expand A tile: one 32-bit mask word per thread -> 32 bf16 into As
        {
            uint32_t mword = reinterpret_cast<const uint32_t*>(sm + CEN_SM_M(buf))[tid];
            __nv_bfloat16* arow = As + lr * STRIDE + q * 32;
#pragma unroll
            for (int u = 0; u < 4; u++)
                *reinterpret_cast<uint4*>(arow + u * 8) =
                    make_uint4(pack2(mword, u * 8), pack2(mword, u * 8 + 2),
                               pack2(mword, u * 8 + 4), pack2(mword, u * 8 + 6));
        }
        __syncthreads();

        const uint32_t bbase = smb + CEN_SM_B(buf);
#pragma unroll
        for (int ks = 0; ks < 8; ks++) {
            const uint32_t kb = ks * 32;
            uint32_t a[2][4], b[2][4];
#pragma unroll
            for (int mt = 0; mt < 2; mt++) ldsm4(a[mt], aoff[mt] + kb);
#pragma unroll
            for (int np = 0; np < 2; np++) ldsm4(b[np], bbase + boffRel[np] + kb);
#pragma unroll
            for (int mt = 0; mt < 2; mt++)
#pragma unroll
                for (int nt = 0; nt < 4; nt++)
                    mma16816(acc[mt][nt], a[mt][0], a[mt][1], a[mt][2], a[mt][3],
                             b[nt >> 1][(nt & 1) * 2], b[nt >> 1][(nt & 1) * 2 + 1]);
        }
    }

    const int g = lane >> 2, tig = lane & 3;
#pragma unroll
    for (int mt = 0; mt < 2; mt++)
#pragma unroll
        for (int h = 0; h < 2; h++) {
            int grow = rowBase + wm * 32 + mt * 16 + h * 8 + g;
#pragma unroll
            for (int nt = 0; nt < 4; nt++) {
                int col = wn * 32 + nt * 8 + tig * 2;
                float2 v = make_float2(acc[mt][nt][h * 2], acc[mt][nt][h * 2 + 1]);
                *reinterpret_cast<float2*>(g_part + ((size_t)blockIdx.y * NN + grow) * DD + col) = v;
            }
        }
}

// ---------------------------------------------------------------------------
// centers combine: sum 4 split partials, /count, write fp32 + bf16 + c2
// ---------------------------------------------------------------------------
__global__ __launch_bounds__(128) void centers_combine() {
    int row = blockIdx.x * 4 + (threadIdx.x >> 5);
    int lane = threadIdx.x & 31;
    float inv = 1.0f / g_cntF[row];
    float4 s = make_float4(0.f, 0.f, 0.f, 0.f);
#pragma unroll
    for (int sp = 0; sp < 4; sp++) {
        float4 p = reinterpret_cast<const float4*>(g_part + ((size_t)sp * NN + row) * DD)[lane];
        s.x += p.x; s.y += p.y; s.z += p.z; s.w += p.w;
    }
    s.x *= inv; s.y *= inv; s.z *= inv; s.w *= inv;
    reinterpret_cast<float4*>(g_centers + (size_t)row * DD)[lane] = s;
    __nv_bfloat162 lo = __floats2bfloat162_rn(s.x, s.y);
    __nv_bfloat162 hi = __floats2bfloat162_rn(s.z, s.w);
    uint2 packed = make_uint2(*reinterpret_cast<uint32_t*>(&lo), *reinterpret_cast<uint32_t*>(&hi));
    reinterpret_cast<uint2*>(g_centersB + (size_t)row * DD)[lane] = packed;
    float c2 = s.x * s.x + s.y * s.y + s.z * s.z + s.w * s.w;
#pragma unroll
    for (int o = 16; o; o >>= 1) c2 += __shfl_xor_sync(0xffffffffu, c2, o);
    if (lane == 0) g_c2[row] = c2;
}

// ---------------------------------------------------------------------------
// argmin HMMA: dot[128 rows, 128 j] = centersB @ Xb^T (K=128), fused argmin.
// grid (8 nb, 64 mb) = 512 CTAs, 512 threads (16 warps 4x4); 8 j-tiles/CTA.
// 2 CTAs/SM: redV/redI alias the dead mask-staging region after the loop.
// ---------------------------------------------------------------------------
#define ARG_SM_B(buf)  (34816 + (buf) * 34816)
#define ARG_SM_M(buf)  (104448 + (buf) * 2048)
#define ARG_SM_X2      108544
#define ARG_SM_C2      112640
#define ARG_SM_RV      104448
#define ARG_SM_RI      106496
#define ARG_SM_TOTAL   113152

__global__ __launch_bounds__(512, 2) void argmin_mma() {
    extern __shared__ __align__(16) char sm[];
    const uint32_t smb = smem_u32(sm);
    float* x2s = reinterpret_cast<float*>(sm + ARG_SM_X2);
    float* c2s = reinterpret_cast<float*>(sm + ARG_SM_C2);
    float* redV = reinterpret_cast<float*>(sm + ARG_SM_RV);
    int*   redI = reinterpret_cast<int*>(sm + ARG_SM_RI);

    const int tid = threadIdx.x;
    const int wid = tid >> 5, lane = tid & 31;
    const int wm = wid >> 2, wn = wid & 3;
    const int g = lane >> 2, tig = lane & 3;
    const int mBase = blockIdx.y * 128;
    const int jBase0 = blockIdx.x * 1024;

    const int lr = tid >> 2, q = tid & 3;

    // prologue: A, B(jt0), M(jt0), x2 (1024 floats), c2 (128 floats)
    {
        uint32_t adst = smb + (uint32_t)(lr * STRIDE + q * 32) * 2;
        const __nv_bfloat16* asrc = g_centersB + (size_t)(mBase + lr) * DD + q * 32;
#pragma unroll
        for (int u = 0; u < 4; u++) CP_ASYNC16(adst + u * 16, asrc + u * 8);
        uint32_t bdst = smb + ARG_SM_B(0) + (uint32_t)(lr * STRIDE + q * 32) * 2;
        const __nv_bfloat16* bsrc = g_Xb + (size_t)(jBase0 + lr) * DD + q * 32;
#pragma unroll
        for (int u = 0; u < 4; u++) CP_ASYNC16(bdst + u * 16, bsrc + u * 8);
        if (tid < 128)
            CP_ASYNC16(smb + ARG_SM_M(0) + tid * 16,
                       g_maskBits + (size_t)(mBase + tid) * NW + (jBase0 >> 5));
        if (tid < 256) CP_ASYNC16(smb + ARG_SM_X2 + tid * 16, g_x2 + jBase0 + tid * 4);
        else if (tid < 288) CP_ASYNC16(smb + ARG_SM_C2 + (tid - 256) * 16, g_c2 + mBase + (tid - 256) * 4);
        CP_COMMIT();
    }

    const int l7 = lane & 7, lid8 = lane >> 3;
    uint32_t aoff[2], boffRel[2];
#pragma unroll
    for (int mt = 0; mt < 2; mt++)
        aoff[mt] = smb + (uint32_t)((wm * 32 + mt * 16 + (lid8 & 1) * 8 + l7) * STRIDE * 2 + (lid8 >> 1) * 16);
#pragma unroll
    for (int np = 0; np < 2; np++)
        boffRel[np] = (uint32_t)((wn * 32 + np * 16 + (lid8 >> 1) * 8 + l7) * STRIDE * 2 + (lid8 & 1) * 16);

    float best[2][2];
    int   bidx[2][2];
#pragma unroll
    for (int mt = 0; mt < 2; mt++)
#pragma unroll
        for (int h = 0; h < 2; h++) { best[mt][h] = FLTMAX; bidx[mt][h] = 0x7FFFFFFF; }

    for (int jt = 0; jt < 8; jt++) {
        const int buf = jt & 1;
        const int jBase = jBase0 + jt * 128;
        CP_WAIT0();
        __syncthreads();

        if (jt + 1 < 8) {
            const int jn = jBase0 + (jt + 1) * 128;
            uint32_t bdst = smb + ARG_SM_B(buf ^ 1) + (uint32_t)(lr * STRIDE + q * 32) * 2;
            const __nv_bfloat16* bsrc = g_Xb + (size_t)(jn + lr) * DD + q * 32;
#pragma unroll
            for (int u = 0; u < 4; u++) CP_ASYNC16(bdst + u * 16, bsrc + u * 8);
            if (tid < 128)
                CP_ASYNC16(smb + ARG_SM_M(buf ^ 1) + tid * 16,
                           g_maskBits + (size_t)(mBase + tid) * NW + (jn >> 5));
            CP_COMMIT();
        }

        float acc[2][4][4];
#pragma unroll
        for (int mt = 0; mt < 2; mt++)
#pragma unroll
            for (int nt = 0; nt < 4; nt++)
#pragma unroll
                for (int qq = 0; qq < 4; qq++) acc[mt][nt][qq] = 0.f;

        const uint32_t bbase = smb + ARG_SM_B(buf);
#pragma unroll
        for (int ks = 0; ks < 8; ks++) {
            const uint32_t kb = ks * 32;
            uint32_t a[2][4], b[2][4];
#pragma unroll
            for (int mt = 0; mt < 2; mt++) ldsm4(a[mt], aoff[mt] + kb);
#pragma unroll
            for (int np = 0; np < 2; np++) ldsm4(b[np], bbase + boffRel[np] + kb);
#pragma unroll
            for (int mt = 0; mt < 2; mt++)
#pragma unroll
                for (int nt = 0; nt < 4; nt++)
                    mma16816(acc[mt][nt], a[mt][0], a[mt][1], a[mt][2], a[mt][3],
                             b[nt >> 1][(nt & 1) * 2], b[nt >> 1][(nt & 1) * 2 + 1]);
        }

        // fused argmin update; mask words from smem
        const uint32_t* Msm = reinterpret_cast<const uint32_t*>(sm + ARG_SM_M(buf));
#pragma unroll
        for (int mt = 0; mt < 2; mt++)
#pragma unroll
            for (int h = 0; h < 2; h++) {
                int lrow = wm * 32 + mt * 16 + h * 8 + g;
                float negc2 = -c2s[lrow];
                uint32_t mw = Msm[lrow * 4 + wn];
                float bb = best[mt][h];
                int bi = bidx[mt][h];
#pragma unroll
                for (int nt = 0; nt < 4; nt++) {
                    int bpos = nt * 8 + tig * 2;
                    int lcol = wn * 32 + bpos;
                    float v0 = fmaxf(fmaf(-2.f, acc[mt][nt][h * 2 + 0], x2s[jt * 128 + lcol + 0]), negc2);
                    float v1 = fmaxf(fmaf(-2.f, acc[mt][nt][h * 2 + 1], x2s[jt * 128 + lcol + 1]), negc2);
                    if ((mw >> bpos) & 1u) v0 = FLTMAX;
                    if ((mw >> (bpos + 1)) & 1u) v1 = FLTMAX;
                    if (v0 < bb) { bb = v0; bi = jBase + lcol; }
                    if (v1 < bb) { bb = v1; bi = jBase + lcol + 1; }
                }
                best[mt][h] = bb;
                bidx[mt][h] = bi;
            }
    }

    // barrier: mask region is about to be reused as reduction scratch
    __syncthreads();

    // final reductions
#pragma unroll
    for (int mt = 0; mt < 2; mt++)
#pragma unroll
        for (int h = 0; h < 2; h++) {
            float bb = best[mt][h];
            int bi = bidx[mt][h];
#pragma unroll
            for (int o = 1; o < 4; o <<= 1) {
                float v = __shfl_down_sync(0xffffffffu, bb, o);
                int   i = __shfl_down_sync(0xffffffffu, bi, o);
                if (v < bb || (v == bb && i < bi)) { bb = v; bi = i; }
            }
            if (tig == 0) {
                int lrow = wm * 32 + mt * 16 + h * 8 + g;
                redV[lrow * 4 + wn] = bb;
                redI[lrow * 4 + wn] = bi;
            }
        }
    __syncthreads();

    if (tid < 128) {
        float bb = redV[tid * 4];
        int bi = redI[tid * 4];
#pragma unroll
        for (int w = 1; w < 4; w++) {
            float v = redV[tid * 4 + w];
            int   i = redI[tid * 4 + w];
            if (v < bb || (v == bb && i < bi)) { bb = v; bi = i; }
        }
        g_blockBest[(size_t)blockIdx.x * NN + mBase + tid] = bb;
        g_blockIdx [(size_t)blockIdx.x * NN + mBase + tid] = bi;
    }
}

// ---------------------------------------------------------------------------
// fused combine + loss + global mean: warp per anchor; block partial sum is
// atomically added to out[0] (pre-zeroed by cudaMemsetAsync).
// ---------------------------------------------------------------------------
__global__ __launch_bounds__(128) void combine_loss_kernel(const float* __restrict__ X,
                                                           float* __restrict__ out) {
    __shared__ float warpSum[4];
    int a = blockIdx.x * 4 + (threadIdx.x >> 5);
    int lane = threadIdx.x & 31;
    float bv = FLTMAX;
    int bi = 0x7FFFFFFF;
    if (lane < 8) {
        bv = g_blockBest[(size_t)lane * NN + a];
        bi = g_blockIdx [(size_t)lane * NN + a];
    }
#pragma unroll
    for (int o = 4; o; o >>= 1) {
        float v = __shfl_down_sync(0xffffffffu, bv, o);
        int   i = __shfl_down_sync(0xffffffffu, bi, o);
        if (v < bv || (v == bv && i < bi)) { bv = v; bi = i; }
    }
    bi = __shfl_sync(0xffffffffu, bi, 0);

    float4 cv = reinterpret_cast<const float4*>(g_centers + (size_t)a * DD)[lane];
    float4 xv = reinterpret_cast<const float4*>(X + (size_t)a * DD)[lane];
    float4 nv = reinterpret_cast<const float4*>(X + (size_t)bi * DD)[lane];
    const float EPS = 1e-6f;
    float t, sap = 0.f, san = 0.f;
    t = cv.x - xv.x + EPS; sap += t * t;
    t = cv.y - xv.y + EPS; sap += t * t;
    t = cv.z - xv.z + EPS; sap += t * t;
    t = cv.w - xv.w + EPS; sap += t * t;
    t = cv.x - nv.x + EPS; san += t * t;
    t = cv.y - nv.y + EPS; san += t * t;
    t = cv.z - nv.z + EPS; san += t * t;
    t = cv.w - nv.w + EPS; san += t * t;
#pragma unroll
    for (int o = 16; o; o >>= 1) {
        sap += __shfl_xor_sync(0xffffffffu, sap, o);
        san += __shfl_xor_sync(0xffffffffu, san, o);
    }
    if (lane == 0)
        warpSum[threadIdx.x >> 5] = fmaxf(sqrtf(sap) - sqrtf(san) + 0.3f, 0.f);
    __syncthreads();
    if (threadIdx.x == 0) {
        float s = (warpSum[0] + warpSum[1]) + (warpSum[2] + warpSum[3]);
        atomicAdd(out, s * (1.0f / NN));
    }
}

// ---------------------------------------------------------------------------
extern "C" void kernel_launch(void* const* d_in, const int* in_sizes, int n_in,
                              void* d_out, int out_size) {
    const float* X;
    const int* S;
    if (in_sizes[0] == NN * DD) {
        X = (const float*)d_in[0];
        S = (const int*)d_in[1];
    } else {
        X = (const float*)d_in[1];
        S = (const int*)d_in[0];
    }

    cudaFuncSetAttribute(centers_mma, cudaFuncAttributeMaxDynamicSharedMemorySize, CEN_SM_TOTAL);
    cudaFuncSetAttribute(argmin_mma, cudaFuncAttributeMaxDynamicSharedMemorySize, ARG_SM_TOTAL);

    cudaMemsetAsync(d_out, 0, sizeof(float), 0);

    pack_kernel<<<NN / 8, 256>>>(S);
    prep_kernel<<<dim3(NN / 32, DD / 32), 256>>>(X);
    x2_kernel<<<NN / 8, 256>>>(X);
    centers_mma<<<dim3(64, 4), 512, CEN_SM_TOTAL>>>();
    centers_combine<<<NN / 4, 128>>>();
    argmin_mma<<<dim3(8, 64), 512, ARG_SM_TOTAL>>>();
    combine_loss_kernel<<<NN / 4, 128>>>(X, (float*)d_out);
}

// round 17
// speedup vs baseline: 1.0739x; 1.0198x over previous
#include <cuda_runtime.h>
#include <cuda_bf16.h>
#include <math.h>
#include <stdint.h>

#define NN 8192
#define DD 128
#define FLTMAX 3.402823466e38f
#define STRIDE 136   // padded bf16 row stride (272B): conflict-free LDSM rows
#define NW 256       // bitmask words per row (8192/32)

// ---------------- device-global scratch (no runtime allocation) -------------
__device__ float          g_centers[(size_t)NN * DD];
__device__ __nv_bfloat16  g_centersB[(size_t)NN * DD];
__device__ __nv_bfloat16  g_Xb [(size_t)NN * DD];   // X bf16 row-major [j][d]
__device__ __nv_bfloat16  g_XbT[(size_t)DD * NN];   // X^T bf16 [d][j]
__device__ uint32_t       g_maskBits[(size_t)NN * NW]; // packed mask bits
__device__ float          g_cntF[NN];
__device__ float          g_x2[NN];
__device__ float          g_c2[NN];
__device__ float          g_part[(size_t)4 * NN * DD];
__device__ float          g_blockBest[(size_t)8 * NN];
__device__ int            g_blockIdx [(size_t)8 * NN];

// ---------------- MMA / LDSM / cp.async helpers ------------------------------
__device__ __forceinline__ void mma16816(float c[4],
                                         uint32_t a0, uint32_t a1, uint32_t a2, uint32_t a3,
                                         uint32_t b0, uint32_t b1) {
    asm volatile(
        "mma.sync.aligned.m16n8k16.row.col.f32.bf16.bf16.f32 "
        "{%0,%1,%2,%3}, {%4,%5,%6,%7}, {%8,%9}, {%0,%1,%2,%3};"
        : "+f"(c[0]), "+f"(c[1]), "+f"(c[2]), "+f"(c[3])
        : "r"(a0), "r"(a1), "r"(a2), "r"(a3), "r"(b0), "r"(b1));
}

__device__ __forceinline__ void ldsm4(uint32_t r[4], uint32_t addr) {
    asm volatile("ldmatrix.sync.aligned.m8n8.x4.shared.b16 {%0,%1,%2,%3}, [%4];"
        : "=r"(r[0]), "=r"(r[1]), "=r"(r[2]), "=r"(r[3]) : "r"(addr));
}

__device__ __forceinline__ uint32_t smem_u32(const void* p) {
    uint32_t a;
    asm("{ .reg .u64 t; cvta.to.shared.u64 t, %1; cvt.u32.u64 %0, t; }" : "=r"(a) : "l"(p));
    return a;
}

#define CP_ASYNC16(dst, src) \
    asm volatile("cp.async.cg.shared.global [%0], [%1], 16;" :: "r"(dst), "l"(src))
#define CP_COMMIT() asm volatile("cp.async.commit_group;" ::: "memory")
#define CP_WAIT0()  asm volatile("cp.async.wait_group 0;" ::: "memory")

// two mask bits (i, i+1) -> packed bf16x2 {0|1, 0|1}
__device__ __forceinline__ uint32_t pack2(uint32_t m, int i) {
    return ((m >> i) & 1u) * 0x3F80u + ((m >> (i + 1)) & 1u) * 0x3F800000u;
}

// ---------------------------------------------------------------------------
// fused prologue: blocks 0..1023 = pack, 1024..2047 = prep, 2048..3071 = x2.
// All three parts are independent; co-scheduling lets prep/x2 fill pack's
// DRAM-wait bubbles without stream/event overhead.
// ---------------------------------------------------------------------------
__global__ __launch_bounds__(256) void prologue_kernel(const int* __restrict__ S,
                                                       const float* __restrict__ X) {
    const int b = blockIdx.x;
    if (b < 1024) {
        // ---- pack: similarity int32 -> bitmask + per-row count (warp/row) ----
        int row = b * 8 + (threadIdx.x >> 5);
        int lane = threadIdx.x & 31;
        const int* src = S + (size_t)row * NN;
        uint32_t* dst = g_maskBits + (size_t)row * NW;
        int cnt = 0;
#pragma unroll 4
        for (int it = 0; it < 64; it++) {
            int base = it * 128;
            uint32_t b0 = __ballot_sync(0xffffffffu, src[base + lane] != 0);
            uint32_t b1 = __ballot_sync(0xffffffffu, src[base + 32 + lane] != 0);
            uint32_t b2 = __ballot_sync(0xffffffffu, src[base + 64 + lane] != 0);
            uint32_t b3 = __ballot_sync(0xffffffffu, src[base + 96 + lane] != 0);
            if (lane == 0) {
                *reinterpret_cast<uint4*>(dst + it * 4) = make_uint4(b0, b1, b2, b3);
                cnt += __popc(b0) + __popc(b1) + __popc(b2) + __popc(b3);
            }
        }
        if (lane == 0) g_cntF[row] = (float)cnt;
    } else if (b < 2048) {
        // ---- prep: Xb (bf16) + XbT (bf16 transposed) via smem transpose ----
        __shared__ float tile[32][33];
        int pb = b - 1024;
        int tx = threadIdx.x & 31, ty = threadIdx.x >> 5;
        int j0 = (pb & 255) * 32, d0 = (pb >> 8) * 32;
#pragma unroll
        for (int jr = ty; jr < 32; jr += 8) {
            float v = X[(size_t)(j0 + jr) * DD + d0 + tx];
            tile[jr][tx] = v;
            g_Xb[(size_t)(j0 + jr) * DD + d0 + tx] = __float2bfloat16_rn(v);
        }
        __syncthreads();
#pragma unroll
        for (int dr = ty; dr < 32; dr += 8)
            g_XbT[(size_t)(d0 + dr) * NN + j0 + tx] = __float2bfloat16_rn(tile[tx][dr]);
    } else {
        // ---- x2: squared norms (warp per row), blocks 2048..3071 ----
        int warp = (b - 2048) * 8 + (threadIdx.x >> 5);
        int lane = threadIdx.x & 31;
        float4 a = reinterpret_cast<const float4*>(X + (size_t)warp * DD)[lane];
        float s = a.x * a.x + a.y * a.y + a.z * a.z + a.w * a.w;
#pragma unroll
        for (int o = 16; o; o >>= 1) s += __shfl_xor_sync(0xffffffffu, s, o);
        if (lane == 0) g_x2[warp] = s;
    }
}

// ---------------------------------------------------------------------------
// centers HMMA: part[128 rows, 128 dims] = mask_bf16 @ XbT over K-split 2048
// grid (64 mb, 4 split) = 256 CTAs, 512 threads (16 warps 4x4), 2 CTAs/SM.
// cp.async double-buffered B + mask words; A expanded into smem per iter.
// ---------------------------------------------------------------------------
#define CEN_SM_B(buf)  (34816 + (buf) * 34816)
#define CEN_SM_M(buf)  (104448 + (buf) * 2048)
#define CEN_SM_TOTAL   108544

__global__ __launch_bounds__(512, 2) void centers_mma() {
    extern __shared__ __align__(16) char sm[];
    const uint32_t smb = smem_u32(sm);
    __nv_bfloat16* As = reinterpret_cast<__nv_bfloat16*>(sm);

    const int tid = threadIdx.x;
    const int wid = tid >> 5, lane = tid & 31;
    const int wm = wid >> 2, wn = wid & 3;          // 4 x 4 warps
    const int rowBase = blockIdx.x * 128;
    const int kBase = blockIdx.y * 2048;

    const int lr = tid >> 2;          // row 0..127
    const int q  = tid & 3;           // 32-elem quarter

    const int l7 = lane & 7, lid8 = lane >> 3;
    uint32_t aoff[2], boffRel[2];
#pragma unroll
    for (int mt = 0; mt < 2; mt++)
        aoff[mt] = smb + (uint32_t)((wm * 32 + mt * 16 + (lid8 & 1) * 8 + l7) * STRIDE * 2 + (lid8 >> 1) * 16);
#pragma unroll
    for (int np = 0; np < 2; np++)
        boffRel[np] = (uint32_t)((wn * 32 + np * 16 + (lid8 >> 1) * 8 + l7) * STRIDE * 2 + (lid8 & 1) * 16);

    float acc[2][4][4];
#pragma unroll
    for (int mt = 0; mt < 2; mt++)
#pragma unroll
        for (int nt = 0; nt < 4; nt++)
#pragma unroll
            for (int qq = 0; qq < 4; qq++) acc[mt][nt][qq] = 0.f;

    // prologue: B + M for iter 0
    {
        uint32_t bdst = smb + CEN_SM_B(0) + (uint32_t)(lr * STRIDE + q * 32) * 2;
        const __nv_bfloat16* bsrc = g_XbT + (size_t)lr * NN + kBase + q * 32;
#pragma unroll
        for (int u = 0; u < 4; u++) CP_ASYNC16(bdst + u * 16, bsrc + u * 8);
        if (tid < 128)
            CP_ASYNC16(smb + CEN_SM_M(0) + tid * 16,
                       g_maskBits + (size_t)(rowBase + tid) * NW + (kBase >> 5));
        CP_COMMIT();
    }

    for (int it = 0; it < 16; it++) {
        const int buf = it & 1;
        CP_WAIT0();
        __syncthreads();

        if (it + 1 < 16) {
            const int k0 = kBase + (it + 1) * 128;
            uint32_t bdst = smb + CEN_SM_B(buf ^ 1) + (uint32_t)(lr * STRIDE + q * 32) * 2;
            const __nv_bfloat16* bsrc = g_XbT + (size_t)lr * NN + k0 + q * 32;
#pragma unroll
            for (int u = 0; u < 4; u++) CP_ASYNC16(bdst + u * 16, bsrc + u * 8);
            if (tid < 128)
                CP_ASYNC16(smb + CEN_SM_M(buf ^ 1) + tid * 16,
                           g_maskBits + (size_t)(rowBase + tid) * NW + (k0 >> 5));
            CP_COMMIT();
        }

        // expand A tile: one 32-bit mask word per thread -> 32 bf16 into As
        {
            uint32_t mword = reinterpret_cast<const uint32_t*>(sm + CEN_SM_M(buf))[tid];
            __nv_bfloat16* arow = As + lr * STRIDE + q * 32;
#pragma unroll
            for (int u = 0; u < 4; u++)
                *reinterpret_cast<uint4*>(arow + u * 8) =
                    make_uint4(pack2(mword, u * 8), pack2(mword, u * 8 + 2),
                               pack2(mword, u * 8 + 4), pack2(mword, u * 8 + 6));
        }
        __syncthreads();

        const uint32_t bbase = smb + CEN_SM_B(buf);
#pragma unroll
        for (int ks = 0; ks < 8; ks++) {
            const uint32_t kb = ks * 32;
            uint32_t a[2][4], b[2][4];
#pragma unroll
            for (int mt = 0; mt < 2; mt++) ldsm4(a[mt], aoff[mt] + kb);
#pragma unroll
            for (int np = 0; np < 2; np++) ldsm4(b[np], bbase + boffRel[np] + kb);
#pragma unroll
            for (int mt = 0; mt < 2; mt++)
#pragma unroll
                for (int nt = 0; nt < 4; nt++)
                    mma16816(acc[mt][nt], a[mt][0], a[mt][1], a[mt][2], a[mt][3],
                             b[nt >> 1][(nt & 1) * 2], b[nt >> 1][(nt & 1) * 2 + 1]);
        }
    }

    const int g = lane >> 2, tig = lane & 3;
#pragma unroll
    for (int mt = 0; mt < 2; mt++)
#pragma unroll
        for (int h = 0; h < 2; h++) {
            int grow = rowBase + wm * 32 + mt * 16 + h * 8 + g;
#pragma unroll
            for (int nt = 0; nt < 4; nt++) {
                int col = wn * 32 + nt * 8 + tig * 2;
                float2 v = make_float2(acc[mt][nt][h * 2], acc[mt][nt][h * 2 + 1]);
                *reinterpret_cast<float2*>(g_part + ((size_t)blockIdx.y * NN + grow) * DD + col) = v;
            }
        }
}

// ---------------------------------------------------------------------------
// centers combine: sum 4 split partials, /count, write fp32 + bf16 + c2
// ---------------------------------------------------------------------------
__global__ __launch_bounds__(128) void centers_combine() {
    int row = blockIdx.x * 4 + (threadIdx.x >> 5);
    int lane = threadIdx.x & 31;
    float inv = 1.0f / g_cntF[row];
    float4 s = make_float4(0.f, 0.f, 0.f, 0.f);
#pragma unroll
    for (int sp = 0; sp < 4; sp++) {
        float4 p = reinterpret_cast<const float4*>(g_part + ((size_t)sp * NN + row) * DD)[lane];
        s.x += p.x; s.y += p.y; s.z += p.z; s.w += p.w;
    }
    s.x *= inv; s.y *= inv; s.z *= inv; s.w *= inv;
    reinterpret_cast<float4*>(g_centers + (size_t)row * DD)[lane] = s;
    __nv_bfloat162 lo = __floats2bfloat162_rn(s.x, s.y);
    __nv_bfloat162 hi = __floats2bfloat162_rn(s.z, s.w);
    uint2 packed = make_uint2(*reinterpret_cast<uint32_t*>(&lo), *reinterpret_cast<uint32_t*>(&hi));
    reinterpret_cast<uint2*>(g_centersB + (size_t)row * DD)[lane] = packed;
    float c2 = s.x * s.x + s.y * s.y + s.z * s.z + s.w * s.w;
#pragma unroll
    for (int o = 16; o; o >>= 1) c2 += __shfl_xor_sync(0xffffffffu, c2, o);
    if (lane == 0) g_c2[row] = c2;
}

// ---------------------------------------------------------------------------
// argmin HMMA: dot[128 rows, 128 j] = centersB @ Xb^T (K=128), fused argmin.
// grid (8 nb, 64 mb) = 512 CTAs, 512 threads (16 warps 4x4); 8 j-tiles/CTA.
// 2 CTAs/SM: redV/redI alias the dead mask-staging region after the loop.
// ---------------------------------------------------------------------------
#define ARG_SM_B(buf)  (34816 + (buf) * 34816)
#define ARG_SM_M(buf)  (104448 + (buf) * 2048)
#define ARG_SM_X2      108544
#define ARG_SM_C2      112640
#define ARG_SM_RV      104448
#define ARG_SM_RI      106496
#define ARG_SM_TOTAL   113152

__global__ __launch_bounds__(512, 2) void argmin_mma() {
    extern __shared__ __align__(16) char sm[];
    const uint32_t smb = smem_u32(sm);
    float* x2s = reinterpret_cast<float*>(sm + ARG_SM_X2);
    float* c2s = reinterpret_cast<float*>(sm + ARG_SM_C2);
    float* redV = reinterpret_cast<float*>(sm + ARG_SM_RV);
    int*   redI = reinterpret_cast<int*>(sm + ARG_SM_RI);

    const int tid = threadIdx.x;
    const int wid = tid >> 5, lane = tid & 31;
    const int wm = wid >> 2, wn = wid & 3;
    const int g = lane >> 2, tig = lane & 3;
    const int mBase = blockIdx.y * 128;
    const int jBase0 = blockIdx.x * 1024;

    const int lr = tid >> 2, q = tid & 3;

    // prologue: A, B(jt0), M(jt0), x2 (1024 floats), c2 (128 floats)
    {
        uint32_t adst = smb + (uint32_t)(lr * STRIDE + q * 32) * 2;
        const __nv_bfloat16* asrc = g_centersB + (size_t)(mBase + lr) * DD + q * 32;
#pragma unroll
        for (int u = 0; u < 4; u++) CP_ASYNC16(adst + u * 16, asrc + u * 8);
        uint32_t bdst = smb + ARG_SM_B(0) + (uint32_t)(lr * STRIDE + q * 32) * 2;
        const __nv_bfloat16* bsrc = g_Xb + (size_t)(jBase0 + lr) * DD + q * 32;
#pragma unroll
        for (int u = 0; u < 4; u++) CP_ASYNC16(bdst + u * 16, bsrc + u * 8);
        if (tid < 128)
            CP_ASYNC16(smb + ARG_SM_M(0) + tid * 16,
                       g_maskBits + (size_t)(mBase + tid) * NW + (jBase0 >> 5));
        if (tid < 256) CP_ASYNC16(smb + ARG_SM_X2 + tid * 16, g_x2 + jBase0 + tid * 4);
        else if (tid < 288) CP_ASYNC16(smb + ARG_SM_C2 + (tid - 256) * 16, g_c2 + mBase + (tid - 256) * 4);
        CP_COMMIT();
    }

    const int l7 = lane & 7, lid8 = lane >> 3;
    uint32_t aoff[2], boffRel[2];
#pragma unroll
    for (int mt = 0; mt < 2; mt++)
        aoff[mt] = smb + (uint32_t)((wm * 32 + mt * 16 + (lid8 & 1) * 8 + l7) * STRIDE * 2 + (lid8 >> 1) * 16);
#pragma unroll
    for (int np = 0; np < 2; np++)
        boffRel[np] = (uint32_t)((wn * 32 + np * 16 + (lid8 >> 1) * 8 + l7) * STRIDE * 2 + (lid8 & 1) * 16);

    float best[2][2];
    int   bidx[2][2];
#pragma unroll
    for (int mt = 0; mt < 2; mt++)
#pragma unroll
        for (int h = 0; h < 2; h++) { best[mt][h] = FLTMAX; bidx[mt][h] = 0x7FFFFFFF; }

    for (int jt = 0; jt < 8; jt++) {
        const int buf = jt & 1;
        const int jBase = jBase0 + jt * 128;
        CP_WAIT0();
        __syncthreads();

        if (jt + 1 < 8) {
            const int jn = jBase0 + (jt + 1) * 128;
            uint32_t bdst = smb + ARG_SM_B(buf ^ 1) + (uint32_t)(lr * STRIDE + q * 32) * 2;
            const __nv_bfloat16* bsrc = g_Xb + (size_t)(jn + lr) * DD + q * 32;
#pragma unroll
            for (int u = 0; u < 4; u++) CP_ASYNC16(bdst + u * 16, bsrc + u * 8);
            if (tid < 128)
                CP_ASYNC16(smb + ARG_SM_M(buf ^ 1) + tid * 16,
                           g_maskBits + (size_t)(mBase + tid) * NW + (jn >> 5));
            CP_COMMIT();
        }

        float acc[2][4][4];
#pragma unroll
        for (int mt = 0; mt < 2; mt++)
#pragma unroll
            for (int nt = 0; nt < 4; nt++)
#pragma unroll
                for (int qq = 0; qq < 4; qq++) acc[mt][nt][qq] = 0.f;

        const uint32_t bbase = smb + ARG_SM_B(buf);
#pragma unroll
        for (int ks = 0; ks < 8; ks++) {
            const uint32_t kb = ks * 32;
            uint32_t a[2][4], b[2][4];
#pragma unroll
            for (int mt = 0; mt < 2; mt++) ldsm4(a[mt], aoff[mt] + kb);
#pragma unroll
            for (int np = 0; np < 2; np++) ldsm4(b[np], bbase + boffRel[np] + kb);
#pragma unroll
            for (int mt = 0; mt < 2; mt++)
#pragma unroll
                for (int nt = 0; nt < 4; nt++)
                    mma16816(acc[mt][nt], a[mt][0], a[mt][1], a[mt][2], a[mt][3],
                             b[nt >> 1][(nt & 1) * 2], b[nt >> 1][(nt & 1) * 2 + 1]);
        }

        // fused argmin update; mask words from smem
        const uint32_t* Msm = reinterpret_cast<const uint32_t*>(sm + ARG_SM_M(buf));
#pragma unroll
        for (int mt = 0; mt < 2; mt++)
#pragma unroll
            for (int h = 0; h < 2; h++) {
                int lrow = wm * 32 + mt * 16 + h * 8 + g;
                float negc2 = -c2s[lrow];
                uint32_t mw = Msm[lrow * 4 + wn];
                float bb = best[mt][h];
                int bi = bidx[mt][h];
#pragma unroll
                for (int nt = 0; nt < 4; nt++) {
                    int bpos = nt * 8 + tig * 2;
                    int lcol = wn * 32 + bpos;
                    float v0 = fmaxf(fmaf(-2.f, acc[mt][nt][h * 2 + 0], x2s[jt * 128 + lcol + 0]), negc2);
                    float v1 = fmaxf(fmaf(-2.f, acc[mt][nt][h * 2 + 1], x2s[jt * 128 + lcol + 1]), negc2);
                    if ((mw >> bpos) & 1u) v0 = FLTMAX;
                    if ((mw >> (bpos + 1)) & 1u) v1 = FLTMAX;
                    if (v0 < bb) { bb = v0; bi = jBase + lcol; }
                    if (v1 < bb) { bb = v1; bi = jBase + lcol + 1; }
                }
                best[mt][h] = bb;
                bidx[mt][h] = bi;
            }
    }

    // barrier: mask region is about to be reused as reduction scratch
    __syncthreads();

    // final reductions
#pragma unroll
    for (int mt = 0; mt < 2; mt++)
#pragma unroll
        for (int h = 0; h < 2; h++) {
            float bb = best[mt][h];
            int bi = bidx[mt][h];
#pragma unroll
            for (int o = 1; o < 4; o <<= 1) {
                float v = __shfl_down_sync(0xffffffffu, bb, o);
                int   i = __shfl_down_sync(0xffffffffu, bi, o);
                if (v < bb || (v == bb && i < bi)) { bb = v; bi = i; }
            }
            if (tig == 0) {
                int lrow = wm * 32 + mt * 16 + h * 8 + g;
                redV[lrow * 4 + wn] = bb;
                redI[lrow * 4 + wn] = bi;
            }
        }
    __syncthreads();

    if (tid < 128) {
        float bb = redV[tid * 4];
        int bi = redI[tid * 4];
#pragma unroll
        for (int w = 1; w < 4; w++) {
            float v = redV[tid * 4 + w];
            int   i = redI[tid * 4 + w];
            if (v < bb || (v == bb && i < bi)) { bb = v; bi = i; }
        }
        g_blockBest[(size_t)blockIdx.x * NN + mBase + tid] = bb;
        g_blockIdx [(size_t)blockIdx.x * NN + mBase + tid] = bi;
    }
}

// ---------------------------------------------------------------------------
// fused combine + loss + global mean: warp per anchor; block partial sum is
// atomically added to out[0] (pre-zeroed by cudaMemsetAsync).
// ---------------------------------------------------------------------------
__global__ __launch_bounds__(128) void combine_loss_kernel(const float* __restrict__ X,
                                                           float* __restrict__ out) {
    __shared__ float warpSum[4];
    int a = blockIdx.x * 4 + (threadIdx.x >> 5);
    int lane = threadIdx.x & 31;
    float bv = FLTMAX;
    int bi = 0x7FFFFFFF;
    if (lane < 8) {
        bv = g_blockBest[(size_t)lane * NN + a];
        bi = g_blockIdx [(size_t)lane * NN + a];
    }
#pragma unroll
    for (int o = 4; o; o >>= 1) {
        float v = __shfl_down_sync(0xffffffffu, bv, o);
        int   i = __shfl_down_sync(0xffffffffu, bi, o);
        if (v < bv || (v == bv && i < bi)) { bv = v; bi = i; }
    }
    bi = __shfl_sync(0xffffffffu, bi, 0);

    float4 cv = reinterpret_cast<const float4*>(g_centers + (size_t)a * DD)[lane];
    float4 xv = reinterpret_cast<const float4*>(X + (size_t)a * DD)[lane];
    float4 nv = reinterpret_cast<const float4*>(X + (size_t)bi * DD)[lane];
    const float EPS = 1e-6f;
    float t, sap = 0.f, san = 0.f;
    t = cv.x - xv.x + EPS; sap += t * t;
    t = cv.y - xv.y + EPS; sap += t * t;
    t = cv.z - xv.z + EPS; sap += t * t;
    t = cv.w - xv.w + EPS; sap += t * t;
    t = cv.x - nv.x + EPS; san += t * t;
    t = cv.y - nv.y + EPS; san += t * t;
    t = cv.z - nv.z + EPS; san += t * t;
    t = cv.w - nv.w + EPS; san += t * t;
#pragma unroll
    for (int o = 16; o; o >>= 1) {
        sap += __shfl_xor_sync(0xffffffffu, sap, o);
        san += __shfl_xor_sync(0xffffffffu, san, o);
    }
    if (lane == 0)
        warpSum[threadIdx.x >> 5] = fmaxf(sqrtf(sap) - sqrtf(san) + 0.3f, 0.f);
    __syncthreads();
    if (threadIdx.x == 0) {
        float s = (warpSum[0] + warpSum[1]) + (warpSum[2] + warpSum[3]);
        atomicAdd(out, s * (1.0f / NN));
    }
}

// ---------------------------------------------------------------------------
extern "C" void kernel_launch(void* const* d_in, const int* in_sizes, int n_in,
                              void* d_out, int out_size) {
    const float* X;
    const int* S;
    if (in_sizes[0] == NN * DD) {
        X = (const float*)d_in[0];
        S = (const int*)d_in[1];
    } else {
        X = (const float*)d_in[1];
        S = (const int*)d_in[0];
    }

    cudaFuncSetAttribute(centers_mma, cudaFuncAttributeMaxDynamicSharedMemorySize, CEN_SM_TOTAL);
    cudaFuncSetAttribute(argmin_mma, cudaFuncAttributeMaxDynamicSharedMemorySize, ARG_SM_TOTAL);

    cudaMemsetAsync(d_out, 0, sizeof(float), 0);

    prologue_kernel<<<3072, 256>>>(S, X);
    centers_mma<<<dim3(64, 4), 512, CEN_SM_TOTAL>>>();
    centers_combine<<<NN / 4, 128>>>();
    argmin_mma<<<dim3(8, 64), 512, ARG_SM_TOTAL>>>();
    combine_loss_kernel<<<NN / 4, 128>>>(X, (float*)d_out);
}